// round 12
// baseline (speedup 1.0000x reference)
#include <cuda_runtime.h>
#include <cuda_fp16.h>
#include <cstdint>

// Problem dims
#define DD    1024
#define NB    8
#define NS    2048
#define MTOT  (NB * NS)        // 16384
#define NQKV  (3 * DD)         // 3072

// GEMM tiling: block 256x128, 512 threads (16 warps, 4M x 4N), warp 64x32
// BK=64 halves per stage, 2-stage double buffer, 2 CTAs/SM (221KB smem/SM)
#define BM 256
#define BN 128
#define BKH 64                 // K halves per stage
#define LDS_ 72                // NT padded smem stride (halves): 144B rows
#define LDSB_NN 136            // NN B-tile stride (halves): 272B rows
#define A_STH (BM * LDS_)      // 18432 halves
#define BNT_STH (BN * LDS_)    // 9216 halves (NT B tile: 128 rows x 64 k)
#define BNN_STH (BKH * LDSB_NN) // 8704 halves (NN B tile: 64 k-rows x 128 n)
#define STAGE_NT ((A_STH + BNT_STH) * 2)    // 55296 B
#define STAGE_NN ((A_STH + BNN_STH) * 2)    // 54272 B
#define SMEM_NT (2 * STAGE_NT)              // 110592 B
#define SMEM_NN (2 * STAGE_NN)              // 108544 B

// ---------------- scratch (device globals; no runtime allocation) ----------------
__device__ __align__(16) half  g_xh  [(size_t)MTOT * DD];      // fp16(x)
__device__ __align__(16) half  g_wh  [(size_t)NQKV * DD];      // fp16(w^T) [n][k]
__device__ __align__(16) half  g_qkvh[(size_t)MTOT * NQKV];    // fp16(qkv), q pre-scaled
__device__ __align__(16) float g_logits[(size_t)NB * NS * NS]; // attention logits
__device__ __align__(16) half  g_sh [(size_t)NB * NS * NS];    // fp16(softmax)
__device__ __align__(16) half  g_yh [(size_t)MTOT * DD];       // fp16(y)
__device__ __align__(16) half  g_owh[(size_t)DD * DD];         // fp16(out_w) [n][k]

enum { SEG_XH = 0, SEG_WH, SEG_QKVH, SEG_SH, SEG_YH, SEG_OWH };

__device__ __forceinline__ const half* seg_ptr(int id) {
    switch (id) {
        case SEG_XH:   return g_xh;
        case SEG_WH:   return g_wh;
        case SEG_QKVH: return g_qkvh;
        case SEG_SH:   return g_sh;
        case SEG_YH:   return g_yh;
        case SEG_OWH:  return g_owh;
    }
    return nullptr;
}

// ---------------- PTX helpers ----------------
__device__ __forceinline__ uint32_t smem_u32(const void* p) {
    uint32_t a;
    asm("{ .reg .u64 t; cvta.to.shared.u64 t, %1; cvt.u32.u64 %0, t; }" : "=r"(a) : "l"(p));
    return a;
}

#define CP_ASYNC16(dst, src) \
    asm volatile("cp.async.cg.shared.global [%0], [%1], 16;\n" :: "r"(dst), "l"(src))
#define CP_COMMIT() asm volatile("cp.async.commit_group;\n" ::: "memory")
#define CP_WAIT0()  asm volatile("cp.async.wait_group 0;\n" ::: "memory")

__device__ __forceinline__ void ldsm_x4(uint32_t& r0, uint32_t& r1, uint32_t& r2,
                                        uint32_t& r3, uint32_t addr) {
    asm volatile("ldmatrix.sync.aligned.m8n8.x4.shared.b16 {%0,%1,%2,%3}, [%4];"
                 : "=r"(r0), "=r"(r1), "=r"(r2), "=r"(r3) : "r"(addr));
}

__device__ __forceinline__ void ldsm_x4_t(uint32_t& r0, uint32_t& r1, uint32_t& r2,
                                          uint32_t& r3, uint32_t addr) {
    asm volatile("ldmatrix.sync.aligned.m8n8.x4.trans.shared.b16 {%0,%1,%2,%3}, [%4];"
                 : "=r"(r0), "=r"(r1), "=r"(r2), "=r"(r3) : "r"(addr));
}

__device__ __forceinline__ void mma16816(float* d, const uint32_t* a, const uint32_t* b) {
    asm volatile("mma.sync.aligned.m16n8k16.row.col.f32.f16.f16.f32 "
                 "{%0,%1,%2,%3}, {%4,%5,%6,%7}, {%8,%9}, {%0,%1,%2,%3};"
                 : "+f"(d[0]), "+f"(d[1]), "+f"(d[2]), "+f"(d[3])
                 : "r"(a[0]), "r"(a[1]), "r"(a[2]), "r"(a[3]), "r"(b[0]), "r"(b[1]));
}

// ---------------- prep kernels ----------------
__global__ void prep_X(const float* __restrict__ x) {
    long long i4 = (long long)blockIdx.x * blockDim.x + threadIdx.x;
    if (i4 >= (long long)MTOT * DD / 4) return;
    float4 v = reinterpret_cast<const float4*>(x)[i4];
    half2 h0 = __halves2half2(__float2half_rn(v.x), __float2half_rn(v.y));
    half2 h1 = __halves2half2(__float2half_rn(v.z), __float2half_rn(v.w));
    reinterpret_cast<half2*>(g_xh)[i4 * 2 + 0] = h0;
    reinterpret_cast<half2*>(g_xh)[i4 * 2 + 1] = h1;
}

// w is [DD][NQKV] row-major; build g_wh[n][k] = w[k][n] via 32x32 smem transpose
__global__ void prep_W(const float* __restrict__ w) {
    __shared__ half t[32][33];
    const int k0 = blockIdx.x * 32;
    const int n0 = blockIdx.y * 32;
    const int tx = threadIdx.x;
    const int ty = threadIdx.y;
#pragma unroll
    for (int i = 0; i < 32; i += 8) {
        t[ty + i][tx] = __float2half_rn(w[(long long)(k0 + ty + i) * NQKV + n0 + tx]);
    }
    __syncthreads();
#pragma unroll
    for (int i = 0; i < 32; i += 8) {
        g_wh[(long long)(n0 + ty + i) * DD + k0 + tx] = t[tx][ty + i];
    }
}

__global__ void prep_OW(const float* __restrict__ ow) {
    int i4 = blockIdx.x * blockDim.x + threadIdx.x;
    if (i4 >= DD * DD / 4) return;
    float4 v = reinterpret_cast<const float4*>(ow)[i4];
    half2 h0 = __halves2half2(__float2half_rn(v.x), __float2half_rn(v.y));
    half2 h1 = __halves2half2(__float2half_rn(v.z), __float2half_rn(v.w));
    reinterpret_cast<half2*>(g_owh)[i4 * 2 + 0] = h0;
    reinterpret_cast<half2*>(g_owh)[i4 * 2 + 1] = h1;
}

// ---------------- GEMM args ----------------
struct G1 { long long aoff, boff, az, bz; int aid, bid, lda, ldb, K; };

enum { EPI_QKV = 0, EPI_OUT = 1, EPI_LOGITS = 2, EPI_YHI = 3 };

// shared epilogue: acc[i][j] rows m0+wm*64+i*16+(lane>>2)+{0,8},
// cols n0+wn*32+j*8+(lane&3)*2+{0,1}
template <int EPI>
__device__ __forceinline__ void epilogue(float acc[4][4][4], int m0, int n0, int z,
                                         int wm, int wn, int lane,
                                         float* __restrict__ outp,
                                         const float* __restrict__ bias) {
    const int rbase = m0 + wm * 64 + (lane >> 2);
    const int cbase = n0 + wn * 32 + (lane & 3) * 2;
#pragma unroll
    for (int i = 0; i < 4; i++) {
#pragma unroll
        for (int j = 0; j < 4; j++) {
            const int c = cbase + j * 8;
#pragma unroll
            for (int h = 0; h < 2; h++) {
                const int rr = rbase + i * 16 + h * 8;
                float v0 = acc[i][j][2 * h + 0];
                float v1 = acc[i][j][2 * h + 1];
                if (EPI == EPI_QKV) {
                    const float sc = (c < DD) ? 0.03125f : 1.0f;
                    long long o = (long long)rr * NQKV + c;
                    *reinterpret_cast<half2*>(g_qkvh + o) =
                        __halves2half2(__float2half_rn(v0 * sc), __float2half_rn(v1 * sc));
                } else if (EPI == EPI_OUT) {
                    long long o = (long long)rr * DD + c;
                    *reinterpret_cast<float2*>(outp + o) =
                        make_float2(v0 + bias[c], v1 + bias[c + 1]);
                } else if (EPI == EPI_LOGITS) {
                    long long o = ((long long)(z * NS + rr)) * NS + c;
                    *reinterpret_cast<float2*>(g_logits + o) = make_float2(v0, v1);
                } else { // EPI_YHI
                    long long o = ((long long)(z * NS + rr)) * DD + c;
                    *reinterpret_cast<half2*>(g_yh + o) =
                        __halves2half2(__float2half_rn(v0), __float2half_rn(v1));
                }
            }
        }
    }
}

// ---------------- single-term GEMM: 256x128, BK=64, 2-stage, 512 threads ----------------
// BT=false: B is [n][k] (NT).  BT=true: B is [k][n] (NN, ldmatrix.trans)
template <bool BT>
__device__ __forceinline__ void g1_load(const G1& g, int s, int m0, int n0, int z,
                                        uint32_t smb, int tid) {
    const int k0 = s * BKH;
    const half* A = seg_ptr(g.aid) + (long long)z * g.az + g.aoff;
    const half* B = seg_ptr(g.bid) + (long long)z * g.bz + g.boff;
    const uint32_t stage = BT ? STAGE_NN : STAGE_NT;
    const uint32_t sa = smb + (uint32_t)(s & 1) * stage;
    const uint32_t sb = sa + A_STH * 2;
    // A: 256 rows x 128B -> 2048 chunks, 4/thread
#pragma unroll
    for (int i = 0; i < 4; i++) {
        int c = tid + i * 512;
        int r = c >> 3;
        int kc = (c & 7) * 8;
        CP_ASYNC16(sa + (uint32_t)(r * LDS_ + kc) * 2, A + (long long)(m0 + r) * g.lda + k0 + kc);
    }
    if (!BT) {
        // B: 128 n-rows x 128B(k) -> 1024 chunks, 2/thread
#pragma unroll
        for (int i = 0; i < 2; i++) {
            int c = tid + i * 512;
            int r = c >> 3;
            int kc = (c & 7) * 8;
            CP_ASYNC16(sb + (uint32_t)(r * LDS_ + kc) * 2,
                       B + (long long)(n0 + r) * g.ldb + k0 + kc);
        }
    } else {
        // B: 64 k-rows x 256B(n) -> 1024 chunks, 2/thread
#pragma unroll
        for (int i = 0; i < 2; i++) {
            int c = tid + i * 512;
            int r = c >> 4;           // k-row 0..63
            int nc = (c & 15) * 8;    // n col 0..120
            CP_ASYNC16(sb + (uint32_t)(r * LDSB_NN + nc) * 2,
                       B + (long long)(k0 + r) * g.ldb + n0 + nc);
        }
    }
}

template <int EPI, bool BT>
__global__ __launch_bounds__(512, 2) void mg_gemm1(G1 g, float* __restrict__ outp,
                                                   const float* __restrict__ bias) {
    extern __shared__ half sm[];
    const uint32_t smb = smem_u32(sm);
    const int tid  = threadIdx.x;
    const int lane = tid & 31;
    const int wm = (tid >> 5) >> 2;    // 0..3  (M, 64 rows each)
    const int wn = (tid >> 5) & 3;     // 0..3  (N, 32 cols each)
    const int m0 = blockIdx.y * BM;
    const int n0 = blockIdx.x * BN;
    const int z  = blockIdx.z;

    float acc[4][4][4];
#pragma unroll
    for (int i = 0; i < 4; i++)
#pragma unroll
        for (int j = 0; j < 4; j++)
#pragma unroll
            for (int e = 0; e < 4; e++) acc[i][j][e] = 0.0f;

    const int S = g.K / BKH;
    g1_load<BT>(g, 0, m0, n0, z, smb, tid);
    CP_COMMIT();

    const uint32_t stage = BT ? STAGE_NN : STAGE_NT;
    for (int s = 0; s < S; s++) {
        CP_WAIT0();                    // stage s resident (prefetch from prev iter)
        __syncthreads();               // all warps done reading buffer (s-1)&1
        if (s + 1 < S) { g1_load<BT>(g, s + 1, m0, n0, z, smb, tid); CP_COMMIT(); }

        const uint32_t baseA = smb + (uint32_t)(s & 1) * stage;
        const uint32_t baseB = baseA + A_STH * 2;
#pragma unroll
        for (int kk = 0; kk < 4; kk++) {
            uint32_t a[4][4];
#pragma unroll
            for (int i = 0; i < 4; i++) {
                uint32_t addr = baseA + (uint32_t)(
                    (wm * 64 + i * 16 + (lane & 15)) * LDS_ + kk * 16 + (lane >> 4) * 8) * 2;
                ldsm_x4(a[i][0], a[i][1], a[i][2], a[i][3], addr);
            }
#pragma unroll
            for (int j2 = 0; j2 < 2; j2++) {
                uint32_t b[2][2];
                uint32_t t0, t1, t2, t3;
                if (!BT) {
                    uint32_t addr = baseB + (uint32_t)(
                        (wn * 32 + j2 * 16 + (lane & 7) + ((lane >> 4) & 1) * 8) * LDS_
                        + kk * 16 + ((lane >> 3) & 1) * 8) * 2;
                    ldsm_x4(t0, t1, t2, t3, addr);
                } else {
                    uint32_t addr = baseB + (uint32_t)(
                        (kk * 16 + (lane & 7) + ((lane >> 3) & 1) * 8) * LDSB_NN
                        + wn * 32 + j2 * 16 + ((lane >> 4) & 1) * 8) * 2;
                    ldsm_x4_t(t0, t1, t2, t3, addr);
                }
                b[0][0] = t0; b[0][1] = t1; b[1][0] = t2; b[1][1] = t3;
#pragma unroll
                for (int jj = 0; jj < 2; jj++)
#pragma unroll
                    for (int i = 0; i < 4; i++) mma16816(acc[i][2 * j2 + jj], a[i], b[jj]);
            }
        }
    }
    CP_WAIT0();
    epilogue<EPI>(acc, m0, n0, z, wm, wn, lane, outp, bias);
}

// ---------------- softmax: 512 threads, float4, one row per block ----------------
__global__ __launch_bounds__(512) void softmax_kernel() {
    const long long row = blockIdx.x;
    const float* __restrict__ L = g_logits + row * (long long)NS;
    const int tid = threadIdx.x;

    float4 v = reinterpret_cast<const float4*>(L)[tid];
    float mx = fmaxf(fmaxf(v.x, v.y), fmaxf(v.z, v.w));
#pragma unroll
    for (int o = 16; o; o >>= 1) mx = fmaxf(mx, __shfl_xor_sync(0xffffffffu, mx, o));
    __shared__ float smax[16];
    __shared__ float ssum[16];
    if ((tid & 31) == 0) smax[tid >> 5] = mx;
    __syncthreads();
    float bmax = smax[0];
#pragma unroll
    for (int i = 1; i < 16; i++) bmax = fmaxf(bmax, smax[i]);

    v.x = __expf(v.x - bmax);
    v.y = __expf(v.y - bmax);
    v.z = __expf(v.z - bmax);
    v.w = __expf(v.w - bmax);
    float s = (v.x + v.y) + (v.z + v.w);
#pragma unroll
    for (int o = 16; o; o >>= 1) s += __shfl_xor_sync(0xffffffffu, s, o);
    if ((tid & 31) == 0) ssum[tid >> 5] = s;
    __syncthreads();
    float tot = 0.0f;
#pragma unroll
    for (int i = 0; i < 16; i++) tot += ssum[i];
    float inv = 1.0f / tot;

    half2 h0 = __halves2half2(__float2half_rn(v.x * inv), __float2half_rn(v.y * inv));
    half2 h1 = __halves2half2(__float2half_rn(v.z * inv), __float2half_rn(v.w * inv));
    half2* dst = reinterpret_cast<half2*>(g_sh + row * NS) + tid * 2;
    dst[0] = h0;
    dst[1] = h1;
}

// ---------------- launch ----------------
extern "C" void kernel_launch(void* const* d_in, const int* in_sizes, int n_in,
                              void* d_out, int out_size) {
    const float *x = nullptr, *wq = nullptr, *ow = nullptr, *ob = nullptr;
    for (int i = 0; i < n_in; i++) {
        long long sz = in_sizes[i];
        if (sz == (long long)MTOT * DD)      x  = (const float*)d_in[i];
        else if (sz == (long long)DD * NQKV) wq = (const float*)d_in[i];
        else if (sz == (long long)DD * DD)   ow = (const float*)d_in[i];
        else if (sz == DD)                   ob = (const float*)d_in[i];
    }
    if (!x)  x  = (const float*)d_in[0];
    if (!wq) wq = (const float*)d_in[1];
    if (!ow) ow = (const float*)d_in[2];
    if (!ob) ob = (const float*)d_in[3];
    float* out = (float*)d_out;

    cudaFuncSetAttribute((const void*)mg_gemm1<EPI_QKV, false>,
                         cudaFuncAttributeMaxDynamicSharedMemorySize, SMEM_NT);
    cudaFuncSetAttribute((const void*)mg_gemm1<EPI_OUT, false>,
                         cudaFuncAttributeMaxDynamicSharedMemorySize, SMEM_NT);
    cudaFuncSetAttribute((const void*)mg_gemm1<EPI_LOGITS, false>,
                         cudaFuncAttributeMaxDynamicSharedMemorySize, SMEM_NT);
    cudaFuncSetAttribute((const void*)mg_gemm1<EPI_YHI, true>,
                         cudaFuncAttributeMaxDynamicSharedMemorySize, SMEM_NN);

    prep_X<<<(int)(((long long)MTOT * DD / 4) / 256), 256>>>(x);
    prep_W<<<dim3(DD / 32, NQKV / 32), dim3(32, 8)>>>(wq);
    prep_OW<<<(DD * DD / 4) / 256, 256>>>(ow);

    // 1) QKV: [16384 x 1024] * [3072 x 1024]^T -> fp16 qkv (q pre-scaled)
    {
        G1 g{};
        g.aid = SEG_XH; g.aoff = 0; g.az = 0; g.lda = DD;
        g.bid = SEG_WH; g.boff = 0; g.bz = 0; g.ldb = DD;
        g.K = DD;
        mg_gemm1<EPI_QKV, false><<<dim3(NQKV / BN, MTOT / BM, 1), 512, SMEM_NT>>>(g, nullptr, nullptr);
    }
    // 2) QK^T per batch -> fp32 logits (NT: K rows of qkv as B[n][k])
    {
        G1 g{};
        g.aid = SEG_QKVH; g.aoff = 0;
        g.bid = SEG_QKVH; g.boff = DD;
        g.lda = NQKV; g.ldb = NQKV;
        g.az = (long long)NS * NQKV; g.bz = (long long)NS * NQKV;
        g.K = DD;
        mg_gemm1<EPI_LOGITS, false><<<dim3(NS / BN, NS / BM, NB), 512, SMEM_NT>>>(g, nullptr, nullptr);
    }
    // 3) softmax rows -> fp16 probs
    softmax_kernel<<<MTOT, 512>>>();
    // 4) S*V per batch -> fp16 y.  NN: B = V band of qkv, native [k][n] layout.
    {
        G1 g{};
        g.aid = SEG_SH;   g.aoff = 0;      g.lda = NS;
        g.bid = SEG_QKVH; g.boff = 2 * DD; g.ldb = NQKV;
        g.az = (long long)NS * NS; g.bz = (long long)NS * NQKV;
        g.K = NS;
        mg_gemm1<EPI_YHI, true><<<dim3(DD / BN, NS / BM, NB), 512, SMEM_NN>>>(g, nullptr, nullptr);
    }
    // 5) out = yh @ owh^T + b
    {
        G1 g{};
        g.aid = SEG_YH;  g.aoff = 0; g.az = 0; g.lda = DD;
        g.bid = SEG_OWH; g.boff = 0; g.bz = 0; g.ldb = DD;
        g.K = DD;
        mg_gemm1<EPI_OUT, false><<<dim3(DD / BN, MTOT / BM, 1), 512, SMEM_NT>>>(g, out, ob);
    }
}

// round 13
// speedup vs baseline: 5.7255x; 5.7255x over previous
#include <cuda_runtime.h>
#include <cuda_fp16.h>
#include <cstdint>

// Problem dims
#define DD    1024
#define NB    8
#define NS    2048
#define MTOT  (NB * NS)        // 16384
#define NQKV  (3 * DD)         // 3072

// GEMM tiling: block 128x128, 256 threads (8 warps, 2M x 4N), warp 64x32
// BK=64 halves per stage, 2-stage double buffer, 2 CTAs/SM (RF-exact: 2*256*124 regs)
#define BM 128
#define BN 128
#define BKH 64                 // K halves per stage
#define LDS_ 72                // NT padded smem stride (halves): 144B rows
#define LDSB_NN 136            // NN B-tile stride (halves): 272B rows
#define A_STH (BM * LDS_)      // 9216 halves
#define BNT_STH (BN * LDS_)    // 9216 halves (NT B tile: 128 rows x 64 k)
#define BNN_STH (BKH * LDSB_NN) // 8704 halves (NN B tile: 64 k-rows x 128 n)
#define STAGE_NT ((A_STH + BNT_STH) * 2)    // 36864 B
#define STAGE_NN ((A_STH + BNN_STH) * 2)    // 35840 B
#define SMEM_NT (2 * STAGE_NT)              // 73728 B
#define SMEM_NN (2 * STAGE_NN)              // 71680 B

// epilogue staging: per-warp 64x32 region, stride 40 halves (bank-perm 20r mod 32)
#define EPI_STRIDE 40
#define EPI_WBUF_H (64 * EPI_STRIDE)        // 2560 halves = 5120 B per warp; 8 warps = 40KB

// ---------------- scratch (device globals; no runtime allocation) ----------------
__device__ __align__(16) half  g_xh  [(size_t)MTOT * DD];      // fp16(x)
__device__ __align__(16) half  g_wh  [(size_t)NQKV * DD];      // fp16(w^T) [n][k]
__device__ __align__(16) half  g_qkvh[(size_t)MTOT * NQKV];    // fp16(qkv), q pre-scaled
__device__ __align__(16) float g_logits[(size_t)NB * NS * NS]; // attention logits
__device__ __align__(16) half  g_sh [(size_t)NB * NS * NS];    // fp16(softmax)
__device__ __align__(16) half  g_yh [(size_t)MTOT * DD];       // fp16(y)
__device__ __align__(16) half  g_owh[(size_t)DD * DD];         // fp16(out_w) [n][k]

enum { SEG_XH = 0, SEG_WH, SEG_QKVH, SEG_SH, SEG_YH, SEG_OWH };

__device__ __forceinline__ const half* seg_ptr(int id) {
    switch (id) {
        case SEG_XH:   return g_xh;
        case SEG_WH:   return g_wh;
        case SEG_QKVH: return g_qkvh;
        case SEG_SH:   return g_sh;
        case SEG_YH:   return g_yh;
        case SEG_OWH:  return g_owh;
    }
    return nullptr;
}

// ---------------- PTX helpers ----------------
__device__ __forceinline__ uint32_t smem_u32(const void* p) {
    uint32_t a;
    asm("{ .reg .u64 t; cvta.to.shared.u64 t, %1; cvt.u32.u64 %0, t; }" : "=r"(a) : "l"(p));
    return a;
}

#define CP_ASYNC16(dst, src) \
    asm volatile("cp.async.cg.shared.global [%0], [%1], 16;\n" :: "r"(dst), "l"(src))
#define CP_COMMIT() asm volatile("cp.async.commit_group;\n" ::: "memory")
#define CP_WAIT0()  asm volatile("cp.async.wait_group 0;\n" ::: "memory")

__device__ __forceinline__ void ldsm_x4(uint32_t& r0, uint32_t& r1, uint32_t& r2,
                                        uint32_t& r3, uint32_t addr) {
    asm volatile("ldmatrix.sync.aligned.m8n8.x4.shared.b16 {%0,%1,%2,%3}, [%4];"
                 : "=r"(r0), "=r"(r1), "=r"(r2), "=r"(r3) : "r"(addr));
}

__device__ __forceinline__ void ldsm_x4_t(uint32_t& r0, uint32_t& r1, uint32_t& r2,
                                          uint32_t& r3, uint32_t addr) {
    asm volatile("ldmatrix.sync.aligned.m8n8.x4.trans.shared.b16 {%0,%1,%2,%3}, [%4];"
                 : "=r"(r0), "=r"(r1), "=r"(r2), "=r"(r3) : "r"(addr));
}

__device__ __forceinline__ void mma16816(float* d, const uint32_t* a, const uint32_t* b) {
    asm volatile("mma.sync.aligned.m16n8k16.row.col.f32.f16.f16.f32 "
                 "{%0,%1,%2,%3}, {%4,%5,%6,%7}, {%8,%9}, {%0,%1,%2,%3};"
                 : "+f"(d[0]), "+f"(d[1]), "+f"(d[2]), "+f"(d[3])
                 : "r"(a[0]), "r"(a[1]), "r"(a[2]), "r"(a[3]), "r"(b[0]), "r"(b[1]));
}

// ---------------- prep kernels ----------------
__global__ void prep_X(const float* __restrict__ x) {
    long long i4 = (long long)blockIdx.x * blockDim.x + threadIdx.x;
    if (i4 >= (long long)MTOT * DD / 4) return;
    float4 v = reinterpret_cast<const float4*>(x)[i4];
    half2 h0 = __halves2half2(__float2half_rn(v.x), __float2half_rn(v.y));
    half2 h1 = __halves2half2(__float2half_rn(v.z), __float2half_rn(v.w));
    reinterpret_cast<half2*>(g_xh)[i4 * 2 + 0] = h0;
    reinterpret_cast<half2*>(g_xh)[i4 * 2 + 1] = h1;
}

// w is [DD][NQKV] row-major; build g_wh[n][k] = w[k][n] via 32x32 smem transpose
__global__ void prep_W(const float* __restrict__ w) {
    __shared__ half t[32][33];
    const int k0 = blockIdx.x * 32;
    const int n0 = blockIdx.y * 32;
    const int tx = threadIdx.x;
    const int ty = threadIdx.y;
#pragma unroll
    for (int i = 0; i < 32; i += 8) {
        t[ty + i][tx] = __float2half_rn(w[(long long)(k0 + ty + i) * NQKV + n0 + tx]);
    }
    __syncthreads();
#pragma unroll
    for (int i = 0; i < 32; i += 8) {
        g_wh[(long long)(n0 + ty + i) * DD + k0 + tx] = t[tx][ty + i];
    }
}

__global__ void prep_OW(const float* __restrict__ ow) {
    int i4 = blockIdx.x * blockDim.x + threadIdx.x;
    if (i4 >= DD * DD / 4) return;
    float4 v = reinterpret_cast<const float4*>(ow)[i4];
    half2 h0 = __halves2half2(__float2half_rn(v.x), __float2half_rn(v.y));
    half2 h1 = __halves2half2(__float2half_rn(v.z), __float2half_rn(v.w));
    reinterpret_cast<half2*>(g_owh)[i4 * 2 + 0] = h0;
    reinterpret_cast<half2*>(g_owh)[i4 * 2 + 1] = h1;
}

// ---------------- GEMM args ----------------
struct G1 { long long aoff, boff, az, bz; int aid, bid, lda, ldb, K; };

enum { EPI_QKV = 0, EPI_OUT = 1, EPI_LOGITS = 2, EPI_YHI = 3 };

// shared epilogue: acc[i][j] rows m0+wm*64+i*16+(lane>>2)+{0,8},
// cols n0+wn*32+j*8+(lane&3)*2+{0,1}
// fp16 outputs (QKV, YHI) are staged through smem for coalesced uint4 stores.
template <int EPI>
__device__ __forceinline__ void epilogue(float acc[4][4][4], int m0, int n0, int z,
                                         int wm, int wn, int lane, half* wbuf,
                                         float* __restrict__ outp,
                                         const float* __restrict__ bias) {
    const int rbase = m0 + wm * 64 + (lane >> 2);
    const int cbase = n0 + wn * 32 + (lane & 3) * 2;

    if (EPI == EPI_QKV || EPI == EPI_YHI) {
        // DD boundary aligns with BN=128, so the q-scale is uniform per CTA.
        const float sc = (EPI == EPI_QKV && n0 < DD) ? 0.03125f : 1.0f;
        // stage: local rows i*16+h*8+(lane>>2), local cols j*8+(lane&3)*2
        const int lr0 = (lane >> 2);
        const int lc0 = (lane & 3) * 2;
#pragma unroll
        for (int i = 0; i < 4; i++) {
#pragma unroll
            for (int j = 0; j < 4; j++) {
#pragma unroll
                for (int h = 0; h < 2; h++) {
                    float v0 = acc[i][j][2 * h + 0] * sc;
                    float v1 = acc[i][j][2 * h + 1] * sc;
                    int lrow = i * 16 + h * 8 + lr0;
                    int lcol = j * 8 + lc0;
                    *reinterpret_cast<half2*>(wbuf + lrow * EPI_STRIDE + lcol) =
                        __halves2half2(__float2half_rn(v0), __float2half_rn(v1));
                }
            }
        }
        __syncwarp();
        // drain: 8 iterations, lane covers row t*8+(lane>>2), 16B col chunk (lane&3)*8
        const long long ld  = (EPI == EPI_QKV) ? NQKV : DD;
        half* dst = (EPI == EPI_QKV) ? g_qkvh : g_yh;
        const long long rowoff = (EPI == EPI_QKV) ? 0 : (long long)z * NS;
#pragma unroll
        for (int t = 0; t < 8; t++) {
            int lrow = t * 8 + (lane >> 2);
            int lcol = (lane & 3) * 8;
            uint4 v = *reinterpret_cast<const uint4*>(wbuf + lrow * EPI_STRIDE + lcol);
            long long row = rowoff + m0 + wm * 64 + lrow;
            long long col = n0 + wn * 32 + lcol;
            *reinterpret_cast<uint4*>(dst + row * ld + col) = v;
        }
        return;
    }

#pragma unroll
    for (int i = 0; i < 4; i++) {
#pragma unroll
        for (int j = 0; j < 4; j++) {
            const int c = cbase + j * 8;
#pragma unroll
            for (int h = 0; h < 2; h++) {
                const int rr = rbase + i * 16 + h * 8;
                float v0 = acc[i][j][2 * h + 0];
                float v1 = acc[i][j][2 * h + 1];
                if (EPI == EPI_OUT) {
                    long long o = (long long)rr * DD + c;
                    *reinterpret_cast<float2*>(outp + o) =
                        make_float2(v0 + bias[c], v1 + bias[c + 1]);
                } else { // EPI_LOGITS
                    long long o = ((long long)(z * NS + rr)) * NS + c;
                    *reinterpret_cast<float2*>(g_logits + o) = make_float2(v0, v1);
                }
            }
        }
    }
}

// ---------------- single-term GEMM: BK=64, 2-stage double buffer ----------------
// BT=false: B is [n][k] (NT).  BT=true: B is [k][n] (NN, ldmatrix.trans)
template <bool BT>
__device__ __forceinline__ void g1_load(const G1& g, int s, int m0, int n0, int z,
                                        uint32_t smb, int tid) {
    const int k0 = s * BKH;
    const half* A = seg_ptr(g.aid) + (long long)z * g.az + g.aoff;
    const half* B = seg_ptr(g.bid) + (long long)z * g.bz + g.boff;
    const uint32_t stage = BT ? STAGE_NN : STAGE_NT;
    const uint32_t sa = smb + (uint32_t)(s & 1) * stage;
    const uint32_t sb = sa + A_STH * 2;
    // A: 128 rows x 128B -> 1024 chunks, 4/thread
#pragma unroll
    for (int i = 0; i < 4; i++) {
        int c = tid + i * 256;
        int r = c >> 3;
        int kc = (c & 7) * 8;
        CP_ASYNC16(sa + (uint32_t)(r * LDS_ + kc) * 2, A + (long long)(m0 + r) * g.lda + k0 + kc);
    }
    if (!BT) {
        // B: 128 n-rows x 128B(k) -> 1024 chunks, 4/thread
#pragma unroll
        for (int i = 0; i < 4; i++) {
            int c = tid + i * 256;
            int r = c >> 3;
            int kc = (c & 7) * 8;
            CP_ASYNC16(sb + (uint32_t)(r * LDS_ + kc) * 2,
                       B + (long long)(n0 + r) * g.ldb + k0 + kc);
        }
    } else {
        // B: 64 k-rows x 256B(n) -> 1024 chunks, 4/thread
#pragma unroll
        for (int i = 0; i < 4; i++) {
            int c = tid + i * 256;
            int r = c >> 4;           // k-row 0..63
            int nc = (c & 15) * 8;    // n col 0..120
            CP_ASYNC16(sb + (uint32_t)(r * LDSB_NN + nc) * 2,
                       B + (long long)(k0 + r) * g.ldb + n0 + nc);
        }
    }
}

template <int EPI, bool BT>
__global__ __launch_bounds__(256, 2) void mg_gemm1(G1 g, float* __restrict__ outp,
                                                   const float* __restrict__ bias) {
    extern __shared__ half sm[];
    const uint32_t smb = smem_u32(sm);
    const int tid  = threadIdx.x;
    const int lane = tid & 31;
    const int warp = tid >> 5;
    const int wm = warp >> 2;    // 0..1
    const int wn = warp & 3;     // 0..3
    const int m0 = blockIdx.y * BM;
    const int n0 = blockIdx.x * BN;
    const int z  = blockIdx.z;

    float acc[4][4][4];
#pragma unroll
    for (int i = 0; i < 4; i++)
#pragma unroll
        for (int j = 0; j < 4; j++)
#pragma unroll
            for (int e = 0; e < 4; e++) acc[i][j][e] = 0.0f;

    const int S = g.K / BKH;
    g1_load<BT>(g, 0, m0, n0, z, smb, tid);
    CP_COMMIT();

    const uint32_t stage = BT ? STAGE_NN : STAGE_NT;
    for (int s = 0; s < S; s++) {
        CP_WAIT0();                    // stage s resident (prefetch from prev iter)
        __syncthreads();               // all warps done reading buffer (s-1)&1
        if (s + 1 < S) { g1_load<BT>(g, s + 1, m0, n0, z, smb, tid); CP_COMMIT(); }

        const uint32_t baseA = smb + (uint32_t)(s & 1) * stage;
        const uint32_t baseB = baseA + A_STH * 2;
#pragma unroll
        for (int kk = 0; kk < 4; kk++) {
            uint32_t a[4][4];
#pragma unroll
            for (int i = 0; i < 4; i++) {
                uint32_t addr = baseA + (uint32_t)(
                    (wm * 64 + i * 16 + (lane & 15)) * LDS_ + kk * 16 + (lane >> 4) * 8) * 2;
                ldsm_x4(a[i][0], a[i][1], a[i][2], a[i][3], addr);
            }
#pragma unroll
            for (int j2 = 0; j2 < 2; j2++) {
                uint32_t b[2][2];
                uint32_t t0, t1, t2, t3;
                if (!BT) {
                    uint32_t addr = baseB + (uint32_t)(
                        (wn * 32 + j2 * 16 + (lane & 7) + ((lane >> 4) & 1) * 8) * LDS_
                        + kk * 16 + ((lane >> 3) & 1) * 8) * 2;
                    ldsm_x4(t0, t1, t2, t3, addr);
                } else {
                    uint32_t addr = baseB + (uint32_t)(
                        (kk * 16 + (lane & 7) + ((lane >> 3) & 1) * 8) * LDSB_NN
                        + wn * 32 + j2 * 16 + ((lane >> 4) & 1) * 8) * 2;
                    ldsm_x4_t(t0, t1, t2, t3, addr);
                }
                b[0][0] = t0; b[0][1] = t1; b[1][0] = t2; b[1][1] = t3;
#pragma unroll
                for (int jj = 0; jj < 2; jj++)
#pragma unroll
                    for (int i = 0; i < 4; i++) mma16816(acc[i][2 * j2 + jj], a[i], b[jj]);
            }
        }
    }
    CP_WAIT0();
    __syncthreads();   // before reusing stage smem as epilogue staging buffers
    epilogue<EPI>(acc, m0, n0, z, wm, wn, lane, sm + warp * EPI_WBUF_H, outp, bias);
}

// ---------------- softmax: 512 threads, float4, one row per block ----------------
__global__ __launch_bounds__(512) void softmax_kernel() {
    const long long row = blockIdx.x;
    const float* __restrict__ L = g_logits + row * (long long)NS;
    const int tid = threadIdx.x;

    float4 v = reinterpret_cast<const float4*>(L)[tid];
    float mx = fmaxf(fmaxf(v.x, v.y), fmaxf(v.z, v.w));
#pragma unroll
    for (int o = 16; o; o >>= 1) mx = fmaxf(mx, __shfl_xor_sync(0xffffffffu, mx, o));
    __shared__ float smax[16];
    __shared__ float ssum[16];
    if ((tid & 31) == 0) smax[tid >> 5] = mx;
    __syncthreads();
    float bmax = smax[0];
#pragma unroll
    for (int i = 1; i < 16; i++) bmax = fmaxf(bmax, smax[i]);

    v.x = __expf(v.x - bmax);
    v.y = __expf(v.y - bmax);
    v.z = __expf(v.z - bmax);
    v.w = __expf(v.w - bmax);
    float s = (v.x + v.y) + (v.z + v.w);
#pragma unroll
    for (int o = 16; o; o >>= 1) s += __shfl_xor_sync(0xffffffffu, s, o);
    if ((tid & 31) == 0) ssum[tid >> 5] = s;
    __syncthreads();
    float tot = 0.0f;
#pragma unroll
    for (int i = 0; i < 16; i++) tot += ssum[i];
    float inv = 1.0f / tot;

    half2 h0 = __halves2half2(__float2half_rn(v.x * inv), __float2half_rn(v.y * inv));
    half2 h1 = __halves2half2(__float2half_rn(v.z * inv), __float2half_rn(v.w * inv));
    half2* dst = reinterpret_cast<half2*>(g_sh + row * NS) + tid * 2;
    dst[0] = h0;
    dst[1] = h1;
}

// ---------------- launch ----------------
extern "C" void kernel_launch(void* const* d_in, const int* in_sizes, int n_in,
                              void* d_out, int out_size) {
    const float *x = nullptr, *wq = nullptr, *ow = nullptr, *ob = nullptr;
    for (int i = 0; i < n_in; i++) {
        long long sz = in_sizes[i];
        if (sz == (long long)MTOT * DD)      x  = (const float*)d_in[i];
        else if (sz == (long long)DD * NQKV) wq = (const float*)d_in[i];
        else if (sz == (long long)DD * DD)   ow = (const float*)d_in[i];
        else if (sz == DD)                   ob = (const float*)d_in[i];
    }
    if (!x)  x  = (const float*)d_in[0];
    if (!wq) wq = (const float*)d_in[1];
    if (!ow) ow = (const float*)d_in[2];
    if (!ob) ob = (const float*)d_in[3];
    float* out = (float*)d_out;

    cudaFuncSetAttribute((const void*)mg_gemm1<EPI_QKV, false>,
                         cudaFuncAttributeMaxDynamicSharedMemorySize, SMEM_NT);
    cudaFuncSetAttribute((const void*)mg_gemm1<EPI_OUT, false>,
                         cudaFuncAttributeMaxDynamicSharedMemorySize, SMEM_NT);
    cudaFuncSetAttribute((const void*)mg_gemm1<EPI_LOGITS, false>,
                         cudaFuncAttributeMaxDynamicSharedMemorySize, SMEM_NT);
    cudaFuncSetAttribute((const void*)mg_gemm1<EPI_YHI, true>,
                         cudaFuncAttributeMaxDynamicSharedMemorySize, SMEM_NN);

    prep_X<<<(int)(((long long)MTOT * DD / 4) / 256), 256>>>(x);
    prep_W<<<dim3(DD / 32, NQKV / 32), dim3(32, 8)>>>(wq);
    prep_OW<<<(DD * DD / 4) / 256, 256>>>(ow);

    // 1) QKV: [16384 x 1024] * [3072 x 1024]^T -> fp16 qkv (q pre-scaled)
    {
        G1 g{};
        g.aid = SEG_XH; g.aoff = 0; g.az = 0; g.lda = DD;
        g.bid = SEG_WH; g.boff = 0; g.bz = 0; g.ldb = DD;
        g.K = DD;
        mg_gemm1<EPI_QKV, false><<<dim3(NQKV / BN, MTOT / BM, 1), 256, SMEM_NT>>>(g, nullptr, nullptr);
    }
    // 2) QK^T per batch -> fp32 logits (NT: K rows of qkv as B[n][k])
    {
        G1 g{};
        g.aid = SEG_QKVH; g.aoff = 0;
        g.bid = SEG_QKVH; g.boff = DD;
        g.lda = NQKV; g.ldb = NQKV;
        g.az = (long long)NS * NQKV; g.bz = (long long)NS * NQKV;
        g.K = DD;
        mg_gemm1<EPI_LOGITS, false><<<dim3(NS / BN, NS / BM, NB), 256, SMEM_NT>>>(g, nullptr, nullptr);
    }
    // 3) softmax rows -> fp16 probs
    softmax_kernel<<<MTOT, 512>>>();
    // 4) S*V per batch -> fp16 y.  NN: B = V band of qkv, native [k][n] layout.
    {
        G1 g{};
        g.aid = SEG_SH;   g.aoff = 0;      g.lda = NS;
        g.bid = SEG_QKVH; g.boff = 2 * DD; g.ldb = NQKV;
        g.az = (long long)NS * NS; g.bz = (long long)NS * NQKV;
        g.K = NS;
        mg_gemm1<EPI_YHI, true><<<dim3(DD / BN, NS / BM, NB), 256, SMEM_NN>>>(g, nullptr, nullptr);
    }
    // 5) out = yh @ owh^T + b
    {
        G1 g{};
        g.aid = SEG_YH;  g.aoff = 0; g.az = 0; g.lda = DD;
        g.bid = SEG_OWH; g.boff = 0; g.bz = 0; g.ldb = DD;
        g.K = DD;
        mg_gemm1<EPI_OUT, false><<<dim3(DD / BN, MTOT / BM, 1), 256, SMEM_NT>>>(g, out, ob);
    }
}